// round 1
// baseline (speedup 1.0000x reference)
#include <cuda_runtime.h>
#include <math.h>

#define DM    1024
#define NH    16
#define DKH   64
#define BATCH 2
#define SEQ   2048
#define MTOT  (BATCH*SEQ)   // 4096

// ---------------- scratch (no allocations allowed) ----------------
__device__ float g_Q[MTOT*DM];
__device__ float g_K[MTOT*DM];
__device__ float g_V[MTOT*DM];
__device__ float g_C[MTOT*DM];

// =============================================================
// GEMM:  C[m,n] = sum_k A[m,k] * W[n,k] + bias[n]
// A: M x K row-major, W: N x K row-major (i.e. C = A @ W^T + b)
// Assumes M%128==0, N%128==0, K%16==0 (true here: 4096/1024/1024)
// =============================================================
#define BM  128
#define BN  128
#define BKK 16
#define SPAD 4

__global__ __launch_bounds__(256) void gemm_nt_bias(
    const float* __restrict__ A, const float* __restrict__ W,
    const float* __restrict__ bias, float* __restrict__ C,
    int M, int N, int K)
{
    __shared__ float As[BKK][BM + SPAD];
    __shared__ float Ws[BKK][BN + SPAD];

    const int tid = threadIdx.x;
    const int bm  = blockIdx.y * BM;
    const int bn  = blockIdx.x * BN;
    const int tr  = tid >> 4;          // 0..15
    const int tc  = tid & 15;          // 0..15

    const int lrow = tid >> 2;         // 0..63
    const int lcg  = (tid & 3) << 2;   // 0,4,8,12

    float acc[8][8];
    #pragma unroll
    for (int i = 0; i < 8; i++)
        #pragma unroll
        for (int j = 0; j < 8; j++) acc[i][j] = 0.f;

    for (int k0 = 0; k0 < K; k0 += BKK) {
        __syncthreads();
        #pragma unroll
        for (int s = 0; s < 2; s++) {
            const int row = lrow + s * 64;
            float4 av = *(const float4*)&A[(size_t)(bm + row) * K + k0 + lcg];
            As[lcg + 0][row] = av.x;
            As[lcg + 1][row] = av.y;
            As[lcg + 2][row] = av.z;
            As[lcg + 3][row] = av.w;
            float4 wv = *(const float4*)&W[(size_t)(bn + row) * K + k0 + lcg];
            Ws[lcg + 0][row] = wv.x;
            Ws[lcg + 1][row] = wv.y;
            Ws[lcg + 2][row] = wv.z;
            Ws[lcg + 3][row] = wv.w;
        }
        __syncthreads();

        #pragma unroll
        for (int kk = 0; kk < BKK; kk++) {
            float a[8], w[8];
            #pragma unroll
            for (int i = 0; i < 8; i++) a[i] = As[kk][tr * 8 + i];
            #pragma unroll
            for (int j = 0; j < 8; j++) w[j] = Ws[kk][tc * 8 + j];
            #pragma unroll
            for (int i = 0; i < 8; i++)
                #pragma unroll
                for (int j = 0; j < 8; j++)
                    acc[i][j] += a[i] * w[j];
        }
    }

    float bb[8];
    #pragma unroll
    for (int j = 0; j < 8; j++) bb[j] = bias[bn + tc * 8 + j];

    #pragma unroll
    for (int i = 0; i < 8; i++) {
        const size_t row = (size_t)(bm + tr * 8 + i);
        float4 o0, o1;
        o0.x = acc[i][0] + bb[0]; o0.y = acc[i][1] + bb[1];
        o0.z = acc[i][2] + bb[2]; o0.w = acc[i][3] + bb[3];
        o1.x = acc[i][4] + bb[4]; o1.y = acc[i][5] + bb[5];
        o1.z = acc[i][6] + bb[6]; o1.w = acc[i][7] + bb[7];
        *(float4*)&C[row * N + bn + tc * 8 + 0] = o0;
        *(float4*)&C[row * N + bn + tc * 8 + 4] = o1;
    }
}

// =============================================================
// Attention: for each (b, h, q-tile of 64), stream K/V tiles of 64.
// Unstabilized softmax (matches reference): ctx = (exp(S) @ V) / rowsum(exp(S))
// Q/K/V layout in scratch: [b, t, h*64 + d]  (row stride DM)
// =============================================================
#define BQ 64
#define BT 64
#define SP 65   // smem pitch (odd -> conflict-free column walks)

#define ATTN_SMEM ((4 * BQ * SP + BQ) * (int)sizeof(float))

__global__ __launch_bounds__(256) void attn_kernel(
    const float* __restrict__ Qg, const float* __restrict__ Kg,
    const float* __restrict__ Vg, float* __restrict__ Cg)
{
    extern __shared__ float sm[];
    float* Qs = sm;                 // BQ * SP
    float* Ks = Qs + BQ * SP;       // BT * SP
    float* Vs = Ks + BT * SP;       // BT * SP
    float* Ps = Vs + BT * SP;       // BQ * SP
    float* ds = Ps + BQ * SP;       // BQ

    const int tid = threadIdx.x;
    const int b = blockIdx.z, h = blockIdx.y;
    const int q0 = blockIdx.x * BQ;
    const size_t hb = ((size_t)b * SEQ) * DM + (size_t)h * DKH;

    const int ty = tid >> 4;   // 0..15 -> q rows ty*4..ty*4+3
    const int tx = tid & 15;   // 0..15 -> cols  tx*4..tx*4+3

    // Load Q tile, pre-scaled by 1/sqrt(dk)
    for (int i = tid; i < BQ * DKH / 4; i += 256) {
        const int row = i >> 4;
        const int cg  = (i & 15) << 2;
        float4 v = *(const float4*)&Qg[hb + (size_t)(q0 + row) * DM + cg];
        Qs[row * SP + cg + 0] = v.x * 0.125f;
        Qs[row * SP + cg + 1] = v.y * 0.125f;
        Qs[row * SP + cg + 2] = v.z * 0.125f;
        Qs[row * SP + cg + 3] = v.w * 0.125f;
    }

    float ctx[4][4];
    #pragma unroll
    for (int i = 0; i < 4; i++)
        #pragma unroll
        for (int j = 0; j < 4; j++) ctx[i][j] = 0.f;
    float dreg = 0.f;   // for tid < 64: denominator of q-row `tid`

    for (int k0 = 0; k0 < SEQ; k0 += BT) {
        __syncthreads();   // previous iter's P·V and denom reads done
        for (int i = tid; i < BT * DKH / 4; i += 256) {
            const int row = i >> 4;
            const int cg  = (i & 15) << 2;
            const size_t off = hb + (size_t)(k0 + row) * DM + cg;
            float4 kv = *(const float4*)&Kg[off];
            Ks[row * SP + cg + 0] = kv.x;
            Ks[row * SP + cg + 1] = kv.y;
            Ks[row * SP + cg + 2] = kv.z;
            Ks[row * SP + cg + 3] = kv.w;
            float4 vv = *(const float4*)&Vg[off];
            Vs[row * SP + cg + 0] = vv.x;
            Vs[row * SP + cg + 1] = vv.y;
            Vs[row * SP + cg + 2] = vv.z;
            Vs[row * SP + cg + 3] = vv.w;
        }
        __syncthreads();

        // S = Qs @ Ks^T  (64x64, 4x4 per thread)
        float s[4][4];
        #pragma unroll
        for (int i = 0; i < 4; i++)
            #pragma unroll
            for (int j = 0; j < 4; j++) s[i][j] = 0.f;

        #pragma unroll 8
        for (int d = 0; d < DKH; d++) {
            float qa[4], kb[4];
            #pragma unroll
            for (int i = 0; i < 4; i++) qa[i] = Qs[(ty * 4 + i) * SP + d];
            #pragma unroll
            for (int j = 0; j < 4; j++) kb[j] = Ks[(tx * 4 + j) * SP + d];
            #pragma unroll
            for (int i = 0; i < 4; i++)
                #pragma unroll
                for (int j = 0; j < 4; j++)
                    s[i][j] += qa[i] * kb[j];
        }

        // P = exp(S)
        #pragma unroll
        for (int i = 0; i < 4; i++)
            #pragma unroll
            for (int j = 0; j < 4; j++)
                Ps[(ty * 4 + i) * SP + tx * 4 + j] = __expf(s[i][j]);
        __syncthreads();

        // denominator accumulation (threads 0..63 own one q-row each)
        if (tid < BQ) {
            float t = 0.f;
            #pragma unroll 16
            for (int c = 0; c < BT; c++) t += Ps[tid * SP + c];
            dreg += t;
        }

        // ctx += P @ V
        #pragma unroll 8
        for (int kk = 0; kk < BT; kk++) {
            float pa[4], vb[4];
            #pragma unroll
            for (int i = 0; i < 4; i++) pa[i] = Ps[(ty * 4 + i) * SP + kk];
            #pragma unroll
            for (int j = 0; j < 4; j++) vb[j] = Vs[kk * SP + tx * 4 + j];
            #pragma unroll
            for (int i = 0; i < 4; i++)
                #pragma unroll
                for (int j = 0; j < 4; j++)
                    ctx[i][j] += pa[i] * vb[j];
        }
    }

    __syncthreads();
    if (tid < BQ) ds[tid] = dreg;
    __syncthreads();

    #pragma unroll
    for (int i = 0; i < 4; i++) {
        const float inv = 1.0f / ds[ty * 4 + i];
        float4 o;
        o.x = ctx[i][0] * inv;
        o.y = ctx[i][1] * inv;
        o.z = ctx[i][2] * inv;
        o.w = ctx[i][3] * inv;
        *(float4*)&Cg[hb + (size_t)(q0 + ty * 4 + i) * DM + tx * 4] = o;
    }
}

// =============================================================
// launch
// =============================================================
extern "C" void kernel_launch(void* const* d_in, const int* in_sizes, int n_in,
                              void* d_out, int out_size)
{
    const float* x  = (const float*)d_in[0];
    const float* Wq = (const float*)d_in[1];
    const float* bq = (const float*)d_in[2];
    const float* Wk = (const float*)d_in[3];
    const float* bk = (const float*)d_in[4];
    const float* Wv = (const float*)d_in[5];
    const float* bv = (const float*)d_in[6];
    const float* Wo = (const float*)d_in[7];
    const float* bo = (const float*)d_in[8];
    float* out = (float*)d_out;

    float *Qd, *Kd, *Vd, *Cd;
    cudaGetSymbolAddress((void**)&Qd, g_Q);
    cudaGetSymbolAddress((void**)&Kd, g_K);
    cudaGetSymbolAddress((void**)&Vd, g_V);
    cudaGetSymbolAddress((void**)&Cd, g_C);

    cudaFuncSetAttribute(attn_kernel,
                         cudaFuncAttributeMaxDynamicSharedMemorySize, ATTN_SMEM);

    dim3 gg(DM / BN, MTOT / BM);   // (8, 32)
    gemm_nt_bias<<<gg, 256>>>(x, Wq, bq, Qd, MTOT, DM, DM);
    gemm_nt_bias<<<gg, 256>>>(x, Wk, bk, Kd, MTOT, DM, DM);
    gemm_nt_bias<<<gg, 256>>>(x, Wv, bv, Vd, MTOT, DM, DM);

    dim3 ga(SEQ / BQ, NH, BATCH);  // (32, 16, 2)
    attn_kernel<<<ga, 256, ATTN_SMEM>>>(Qd, Kd, Vd, Cd);

    gemm_nt_bias<<<gg, 256>>>(Cd, Wo, bo, out, MTOT, DM, DM);
}

// round 3
// speedup vs baseline: 2.5367x; 2.5367x over previous
#include <cuda_runtime.h>
#include <cuda_bf16.h>
#include <stdint.h>

#define DM    1024
#define NH    16
#define DKH   64
#define BATCH 2
#define SEQ   2048
#define MTOT  (BATCH*SEQ)   // 4096

typedef __nv_bfloat16 bf16;

// ---------------- scratch (no allocations allowed) ----------------
__device__ bf16 g_xh[MTOT*DM],  g_xl[MTOT*DM];
__device__ bf16 g_wqh[DM*DM], g_wql[DM*DM];
__device__ bf16 g_wkh[DM*DM], g_wkl[DM*DM];
__device__ bf16 g_wvh[DM*DM], g_wvl[DM*DM];
__device__ bf16 g_woh[DM*DM], g_wol[DM*DM];
__device__ bf16 g_Qh[MTOT*DM], g_Ql[MTOT*DM];
__device__ bf16 g_Kh[MTOT*DM], g_Kl[MTOT*DM];
__device__ bf16 g_Vh[MTOT*DM], g_Vl[MTOT*DM];
__device__ bf16 g_Ch[MTOT*DM], g_Cl[MTOT*DM];

// ---------------- helpers ----------------
__device__ __forceinline__ uint32_t smem_u32(const void* p){
    uint32_t a;
    asm("{ .reg .u64 t; cvta.to.shared.u64 t, %1; cvt.u32.u64 %0, t; }" : "=r"(a) : "l"(p));
    return a;
}
__device__ __forceinline__ void ldm4(uint32_t* d, uint32_t a){
    asm volatile("ldmatrix.sync.aligned.m8n8.x4.shared.b16 {%0,%1,%2,%3},[%4];"
        : "=r"(d[0]),"=r"(d[1]),"=r"(d[2]),"=r"(d[3]) : "r"(a));
}
__device__ __forceinline__ void ldm4t(uint32_t* d, uint32_t a){
    asm volatile("ldmatrix.sync.aligned.m8n8.x4.trans.shared.b16 {%0,%1,%2,%3},[%4];"
        : "=r"(d[0]),"=r"(d[1]),"=r"(d[2]),"=r"(d[3]) : "r"(a));
}
__device__ __forceinline__ void mma_bf16(float* c,
    uint32_t a0,uint32_t a1,uint32_t a2,uint32_t a3, uint32_t b0,uint32_t b1){
    asm volatile(
      "mma.sync.aligned.m16n8k16.row.col.f32.bf16.bf16.f32 "
      "{%0,%1,%2,%3},{%4,%5,%6,%7},{%8,%9},{%0,%1,%2,%3};\n"
      : "+f"(c[0]),"+f"(c[1]),"+f"(c[2]),"+f"(c[3])
      : "r"(a0),"r"(a1),"r"(a2),"r"(a3),"r"(b0),"r"(b1));
}
__device__ __forceinline__ uint32_t packbf(bf16 a, bf16 b){
    return ((uint32_t)__bfloat16_as_ushort(b) << 16) | (uint32_t)__bfloat16_as_ushort(a);
}
// split a float pair into hi/lo bf16 pairs and store (4B each)
__device__ __forceinline__ void store_split2(bf16* Hp, bf16* Lp, size_t off, float v0, float v1){
    bf16 h0 = __float2bfloat16_rn(v0), h1 = __float2bfloat16_rn(v1);
    *(uint32_t*)(Hp + off) = packbf(h0, h1);
    bf16 l0 = __float2bfloat16_rn(v0 - __bfloat162float(h0));
    bf16 l1 = __float2bfloat16_rn(v1 - __bfloat162float(h1));
    *(uint32_t*)(Lp + off) = packbf(l0, l1);
}

// ---------------- split kernel: fp32 -> (hi, lo) bf16 ----------------
__global__ void split_kernel(const float* __restrict__ in,
                             bf16* __restrict__ hi, bf16* __restrict__ lo, int n){
    int i = (blockIdx.x * blockDim.x + threadIdx.x) * 4;
    if (i >= n) return;
    float4 v = *(const float4*)(in + i);
    bf16 h0 = __float2bfloat16_rn(v.x), h1 = __float2bfloat16_rn(v.y);
    bf16 h2 = __float2bfloat16_rn(v.z), h3 = __float2bfloat16_rn(v.w);
    uint2 hh, ll;
    hh.x = packbf(h0, h1); hh.y = packbf(h2, h3);
    ll.x = packbf(__float2bfloat16_rn(v.x - __bfloat162float(h0)),
                  __float2bfloat16_rn(v.y - __bfloat162float(h1)));
    ll.y = packbf(__float2bfloat16_rn(v.z - __bfloat162float(h2)),
                  __float2bfloat16_rn(v.w - __bfloat162float(h3)));
    *(uint2*)(hi + i) = hh;
    *(uint2*)(lo + i) = ll;
}

// =============================================================
// Split-bf16 3-pass MMA GEMM:  C[m,n] = sum_k A[m,k]*W[n,k] + bias[n]
// A, W given as hi/lo bf16 arrays.  MODE 0: fp32 out.  MODE 1: split bf16 out, *scale.
// =============================================================
#define GBM 128
#define GBN 128
#define GBK 32
#define GAP 40   // smem pitch (bf16 elems); 80B rows -> conflict-free ldmatrix

template<int MODE>
__global__ __launch_bounds__(256) void gemm_mma(
    const bf16* __restrict__ Ah, const bf16* __restrict__ Al,
    const bf16* __restrict__ Wh, const bf16* __restrict__ Wl,
    const float* __restrict__ bias,
    float* __restrict__ Cf, bf16* __restrict__ Ch, bf16* __restrict__ Cl,
    int M, int N, int K, float scale)
{
    __shared__ bf16 sAh[GBM*GAP], sAl[GBM*GAP], sWh[GBN*GAP], sWl[GBN*GAP];

    const int tid  = threadIdx.x;
    const int wid  = tid >> 5;
    const int lane = tid & 31;
    const int bm   = blockIdx.y * GBM;
    const int bn   = blockIdx.x * GBN;
    const int mwb  = (wid >> 2) * 64;   // warp m offset
    const int nwb  = (wid & 3) * 32;    // warp n offset

    const int g = lane >> 3, r = lane & 7;
    // ldmatrix lane base addrs (byte offsets in shared space)
    const uint32_t aAh = smem_u32(sAh) + (uint32_t)((mwb + (g&1)*8 + r)*GAP + (g>>1)*8)*2;
    const uint32_t aAl = smem_u32(sAl) + (uint32_t)((mwb + (g&1)*8 + r)*GAP + (g>>1)*8)*2;
    const uint32_t aWh = smem_u32(sWh) + (uint32_t)((nwb + (g>>1)*8 + r)*GAP + (g&1)*8)*2;
    const uint32_t aWl = smem_u32(sWl) + (uint32_t)((nwb + (g>>1)*8 + r)*GAP + (g&1)*8)*2;

    const int lrow = tid >> 1;            // 0..127
    const int seg0 = (tid & 1) * 2;       // 0 or 2 (of 4 8-elem segs)

    float acc[4][4][4];
    #pragma unroll
    for (int i = 0; i < 4; i++) {
        #pragma unroll
        for (int j = 0; j < 4; j++) {
            #pragma unroll
            for (int q = 0; q < 4; q++) acc[i][j][q] = 0.f;
        }
    }

    uint4 pAh[2], pAl[2], pWh[2], pWl[2];
    const size_t arow = (size_t)(bm + lrow) * K;
    const size_t wrow = (size_t)(bn + lrow) * K;

    // prefetch stage 0
    #pragma unroll
    for (int u = 0; u < 2; u++){
        int ko = (seg0+u)*8;
        pAh[u] = *(const uint4*)(Ah + arow + ko);
        pAl[u] = *(const uint4*)(Al + arow + ko);
        pWh[u] = *(const uint4*)(Wh + wrow + ko);
        pWl[u] = *(const uint4*)(Wl + wrow + ko);
    }

    const int nst = K / GBK;
    for (int s = 0; s < nst; s++){
        // store staged regs to smem
        #pragma unroll
        for (int u = 0; u < 2; u++){
            int so = lrow*GAP + (seg0+u)*8;
            *(uint4*)(sAh + so) = pAh[u];
            *(uint4*)(sAl + so) = pAl[u];
            *(uint4*)(sWh + so) = pWh[u];
            *(uint4*)(sWl + so) = pWl[u];
        }
        __syncthreads();

        if (s + 1 < nst){
            const size_t k0 = (size_t)(s+1)*GBK;
            #pragma unroll
            for (int u = 0; u < 2; u++){
                size_t ko = k0 + (seg0+u)*8;
                pAh[u] = *(const uint4*)(Ah + arow + ko);
                pAl[u] = *(const uint4*)(Al + arow + ko);
                pWh[u] = *(const uint4*)(Wh + wrow + ko);
                pWl[u] = *(const uint4*)(Wl + wrow + ko);
            }
        }

        #pragma unroll
        for (int kc = 0; kc < 2; kc++){
            uint32_t ah[4][4], al[4][4];
            #pragma unroll
            for (int i = 0; i < 4; i++){
                ldm4(ah[i], aAh + (uint32_t)(i*16*GAP + kc*16)*2);
                ldm4(al[i], aAl + (uint32_t)(i*16*GAP + kc*16)*2);
            }
            #pragma unroll
            for (int jp = 0; jp < 2; jp++){
                uint32_t bh[4], bl[4];
                ldm4(bh, aWh + (uint32_t)(jp*16*GAP + kc*16)*2);
                ldm4(bl, aWl + (uint32_t)(jp*16*GAP + kc*16)*2);
                #pragma unroll
                for (int hh = 0; hh < 2; hh++){
                    const int f = jp*2 + hh;
                    #pragma unroll
                    for (int i = 0; i < 4; i++){
                        mma_bf16(acc[i][f], ah[i][0],ah[i][1],ah[i][2],ah[i][3], bh[2*hh], bh[2*hh+1]);
                        mma_bf16(acc[i][f], ah[i][0],ah[i][1],ah[i][2],ah[i][3], bl[2*hh], bl[2*hh+1]);
                        mma_bf16(acc[i][f], al[i][0],al[i][1],al[i][2],al[i][3], bh[2*hh], bh[2*hh+1]);
                    }
                }
            }
        }
        __syncthreads();
    }

    // epilogue
    #pragma unroll
    for (int f = 0; f < 4; f++){
        const int c = bn + nwb + f*8 + (lane&3)*2;
        const float b0 = bias[c], b1 = bias[c+1];
        #pragma unroll
        for (int i = 0; i < 4; i++){
            const int r0 = bm + mwb + i*16 + (lane>>2);
            const int r1 = r0 + 8;
            float v00 = acc[i][f][0] + b0, v01 = acc[i][f][1] + b1;
            float v10 = acc[i][f][2] + b0, v11 = acc[i][f][3] + b1;
            if (MODE == 0){
                *(float2*)(Cf + (size_t)r0*N + c) = make_float2(v00, v01);
                *(float2*)(Cf + (size_t)r1*N + c) = make_float2(v10, v11);
            } else {
                store_split2(Ch, Cl, (size_t)r0*N + c, v00*scale, v01*scale);
                store_split2(Ch, Cl, (size_t)r1*N + c, v10*scale, v11*scale);
            }
        }
    }
}

// =============================================================
// Attention (flash-style, unstabilized softmax) with split-bf16 MMA.
// Q pre-scaled by 1/sqrt(dk).  Per block: 64 q-rows x one head, 4 warps.
// =============================================================
#define AP 72   // smem pitch (bf16); 144B rows -> conflict-free ldmatrix
#define ATTN_SMEM (6 * 64 * AP * (int)sizeof(bf16))

__global__ __launch_bounds__(128) void attn_mma(
    const bf16* __restrict__ Qh, const bf16* __restrict__ Ql,
    const bf16* __restrict__ Kh, const bf16* __restrict__ Kl,
    const bf16* __restrict__ Vh, const bf16* __restrict__ Vl,
    bf16* __restrict__ Ch, bf16* __restrict__ Cl)
{
    extern __shared__ bf16 sm[];
    bf16* sQh = sm;
    bf16* sQl = sQh + 64*AP;
    bf16* sKh = sQl + 64*AP;
    bf16* sKl = sKh + 64*AP;
    bf16* sVh = sKl + 64*AP;
    bf16* sVl = sVh + 64*AP;

    const int tid  = threadIdx.x;
    const int wid  = tid >> 5;
    const int lane = tid & 31;
    const int b = blockIdx.z, h = blockIdx.y;
    const int q0 = blockIdx.x * 64;
    const size_t hb = ((size_t)b * SEQ) * DM + (size_t)h * DKH;

    const int g = lane >> 3, r = lane & 7;
    const uint32_t aQh = smem_u32(sQh) + (uint32_t)((wid*16 + (g&1)*8 + r)*AP + (g>>1)*8)*2;
    const uint32_t aQl = smem_u32(sQl) + (uint32_t)((wid*16 + (g&1)*8 + r)*AP + (g>>1)*8)*2;
    const uint32_t aKh = smem_u32(sKh) + (uint32_t)(((g>>1)*8 + r)*AP + (g&1)*8)*2;
    const uint32_t aKl = smem_u32(sKl) + (uint32_t)(((g>>1)*8 + r)*AP + (g&1)*8)*2;
    const uint32_t aVh = smem_u32(sVh) + (uint32_t)(((g&1)*8 + r)*AP + (g>>1)*8)*2;
    const uint32_t aVl = smem_u32(sVl) + (uint32_t)(((g&1)*8 + r)*AP + (g>>1)*8)*2;

    // load Q tile (64 x 64) hi/lo
    #pragma unroll
    for (int i = 0; i < 4; i++){
        int idx = tid + i*128;
        int row = idx >> 3, seg = idx & 7;
        size_t go = hb + (size_t)(q0 + row)*DM + seg*8;
        *(uint4*)(sQh + row*AP + seg*8) = *(const uint4*)(Qh + go);
        *(uint4*)(sQl + row*AP + seg*8) = *(const uint4*)(Ql + go);
    }
    __syncthreads();

    uint32_t qh[4][4], ql[4][4];
    #pragma unroll
    for (int kc = 0; kc < 4; kc++){
        ldm4(qh[kc], aQh + kc*32);
        ldm4(ql[kc], aQl + kc*32);
    }

    float o[8][4];
    #pragma unroll
    for (int f = 0; f < 8; f++){
        #pragma unroll
        for (int q = 0; q < 4; q++) o[f][q] = 0.f;
    }
    float dr0 = 0.f, dr1 = 0.f;

    for (int t0 = 0; t0 < SEQ; t0 += 64){
        __syncthreads();
        // load K/V tiles hi/lo
        #pragma unroll
        for (int i = 0; i < 4; i++){
            int idx = tid + i*128;
            int row = idx >> 3, seg = idx & 7;
            size_t go = hb + (size_t)(t0 + row)*DM + seg*8;
            int so = row*AP + seg*8;
            *(uint4*)(sKh + so) = *(const uint4*)(Kh + go);
            *(uint4*)(sKl + so) = *(const uint4*)(Kl + go);
            *(uint4*)(sVh + so) = *(const uint4*)(Vh + go);
            *(uint4*)(sVl + so) = *(const uint4*)(Vl + go);
        }
        __syncthreads();

        // S = Q K^T  (16 x 64 per warp)
        float s[8][4];
        #pragma unroll
        for (int f = 0; f < 8; f++){
            #pragma unroll
            for (int q = 0; q < 4; q++) s[f][q] = 0.f;
        }

        #pragma unroll
        for (int kc = 0; kc < 4; kc++){
            #pragma unroll
            for (int jp = 0; jp < 4; jp++){
                uint32_t kbh[4], kbl[4];
                ldm4(kbh, aKh + (uint32_t)(jp*16*AP)*2 + kc*32);
                ldm4(kbl, aKl + (uint32_t)(jp*16*AP)*2 + kc*32);
                #pragma unroll
                for (int hh = 0; hh < 2; hh++){
                    const int f = jp*2 + hh;
                    mma_bf16(s[f], qh[kc][0],qh[kc][1],qh[kc][2],qh[kc][3], kbh[2*hh], kbh[2*hh+1]);
                    mma_bf16(s[f], qh[kc][0],qh[kc][1],qh[kc][2],qh[kc][3], kbl[2*hh], kbl[2*hh+1]);
                    mma_bf16(s[f], ql[kc][0],ql[kc][1],ql[kc][2],ql[kc][3], kbh[2*hh], kbh[2*hh+1]);
                }
            }
        }

        // P = exp(S): rowsums + in-register split to A-fragments
        uint32_t ph[8][2], pl[8][2];
        #pragma unroll
        for (int f = 0; f < 8; f++){
            float p0 = __expf(s[f][0]), p1 = __expf(s[f][1]);
            float p2 = __expf(s[f][2]), p3 = __expf(s[f][3]);
            dr0 += p0 + p1;  dr1 += p2 + p3;
            bf16 h0=__float2bfloat16_rn(p0), h1=__float2bfloat16_rn(p1);
            bf16 h2=__float2bfloat16_rn(p2), h3=__float2bfloat16_rn(p3);
            ph[f][0] = packbf(h0,h1);  ph[f][1] = packbf(h2,h3);
            pl[f][0] = packbf(__float2bfloat16_rn(p0-__bfloat162float(h0)),
                              __float2bfloat16_rn(p1-__bfloat162float(h1)));
            pl[f][1] = packbf(__float2bfloat16_rn(p2-__bfloat162float(h2)),
                              __float2bfloat16_rn(p3-__bfloat162float(h3)));
        }

        // ctx += P V
        #pragma unroll
        for (int kc = 0; kc < 4; kc++){
            const uint32_t ah0 = ph[2*kc][0], ah1 = ph[2*kc][1];
            const uint32_t ah2 = ph[2*kc+1][0], ah3 = ph[2*kc+1][1];
            const uint32_t al0 = pl[2*kc][0], al1 = pl[2*kc][1];
            const uint32_t al2 = pl[2*kc+1][0], al3 = pl[2*kc+1][1];
            #pragma unroll
            for (int jp = 0; jp < 4; jp++){
                uint32_t vbh[4], vbl[4];
                ldm4t(vbh, aVh + (uint32_t)(kc*16*AP)*2 + jp*32);
                ldm4t(vbl, aVl + (uint32_t)(kc*16*AP)*2 + jp*32);
                #pragma unroll
                for (int hh = 0; hh < 2; hh++){
                    const int f = jp*2 + hh;
                    mma_bf16(o[f], ah0,ah1,ah2,ah3, vbh[2*hh], vbh[2*hh+1]);
                    mma_bf16(o[f], ah0,ah1,ah2,ah3, vbl[2*hh], vbl[2*hh+1]);
                    mma_bf16(o[f], al0,al1,al2,al3, vbh[2*hh], vbh[2*hh+1]);
                }
            }
        }
    }

    // denominators (reduce over the 4 lanes of each row-quad)
    float d0 = dr0, d1 = dr1;
    d0 += __shfl_xor_sync(0xffffffffu, d0, 1);
    d0 += __shfl_xor_sync(0xffffffffu, d0, 2);
    d1 += __shfl_xor_sync(0xffffffffu, d1, 1);
    d1 += __shfl_xor_sync(0xffffffffu, d1, 2);
    const float inv0 = 1.0f / d0, inv1 = 1.0f / d1;

    const int r0 = q0 + wid*16 + (lane>>2);
    const int r1 = r0 + 8;
    #pragma unroll
    for (int f = 0; f < 8; f++){
        const int c = f*8 + (lane&3)*2;
        store_split2(Ch, Cl, hb + (size_t)r0*DM + c, o[f][0]*inv0, o[f][1]*inv0);
        store_split2(Ch, Cl, hb + (size_t)r1*DM + c, o[f][2]*inv1, o[f][3]*inv1);
    }
}

// =============================================================
// launch
// =============================================================
extern "C" void kernel_launch(void* const* d_in, const int* in_sizes, int n_in,
                              void* d_out, int out_size)
{
    const float* x  = (const float*)d_in[0];
    const float* Wq = (const float*)d_in[1];
    const float* bq = (const float*)d_in[2];
    const float* Wk = (const float*)d_in[3];
    const float* bk = (const float*)d_in[4];
    const float* Wv = (const float*)d_in[5];
    const float* bv = (const float*)d_in[6];
    const float* Wo = (const float*)d_in[7];
    const float* bo = (const float*)d_in[8];
    float* out = (float*)d_out;

    bf16 *xh,*xl,*wqh,*wql,*wkh,*wkl,*wvh,*wvl,*woh,*wol;
    bf16 *qhp,*qlp,*khp,*klp,*vhp,*vlp,*chp,*clp;
    cudaGetSymbolAddress((void**)&xh,  g_xh);  cudaGetSymbolAddress((void**)&xl,  g_xl);
    cudaGetSymbolAddress((void**)&wqh, g_wqh); cudaGetSymbolAddress((void**)&wql, g_wql);
    cudaGetSymbolAddress((void**)&wkh, g_wkh); cudaGetSymbolAddress((void**)&wkl, g_wkl);
    cudaGetSymbolAddress((void**)&wvh, g_wvh); cudaGetSymbolAddress((void**)&wvl, g_wvl);
    cudaGetSymbolAddress((void**)&woh, g_woh); cudaGetSymbolAddress((void**)&wol, g_wol);
    cudaGetSymbolAddress((void**)&qhp, g_Qh);  cudaGetSymbolAddress((void**)&qlp, g_Ql);
    cudaGetSymbolAddress((void**)&khp, g_Kh);  cudaGetSymbolAddress((void**)&klp, g_Kl);
    cudaGetSymbolAddress((void**)&vhp, g_Vh);  cudaGetSymbolAddress((void**)&vlp, g_Vl);
    cudaGetSymbolAddress((void**)&chp, g_Ch);  cudaGetSymbolAddress((void**)&clp, g_Cl);

    cudaFuncSetAttribute(attn_mma, cudaFuncAttributeMaxDynamicSharedMemorySize, ATTN_SMEM);

    // splits
    split_kernel<<<(MTOT*DM/4 + 255)/256, 256>>>(x,  xh,  xl,  MTOT*DM);
    split_kernel<<<(DM*DM/4 + 255)/256, 256>>>(Wq, wqh, wql, DM*DM);
    split_kernel<<<(DM*DM/4 + 255)/256, 256>>>(Wk, wkh, wkl, DM*DM);
    split_kernel<<<(DM*DM/4 + 255)/256, 256>>>(Wv, wvh, wvl, DM*DM);
    split_kernel<<<(DM*DM/4 + 255)/256, 256>>>(Wo, woh, wol, DM*DM);

    dim3 gg(DM/GBN, MTOT/GBM);   // (8, 32)
    const float qscale = 0.125f; // 1/sqrt(64)
    gemm_mma<1><<<gg, 256>>>(xh, xl, wqh, wql, bq, nullptr, qhp, qlp, MTOT, DM, DM, qscale);
    gemm_mma<1><<<gg, 256>>>(xh, xl, wkh, wkl, bk, nullptr, khp, klp, MTOT, DM, DM, 1.0f);
    gemm_mma<1><<<gg, 256>>>(xh, xl, wvh, wvl, bv, nullptr, vhp, vlp, MTOT, DM, DM, 1.0f);

    dim3 ga(SEQ/64, NH, BATCH);  // (32, 16, 2)
    attn_mma<<<ga, 128, ATTN_SMEM>>>(qhp, qlp, khp, klp, vhp, vlp, chp, clp);

    gemm_mma<0><<<gg, 256>>>(chp, clp, woh, wol, bo, out, nullptr, nullptr, MTOT, DM, DM, 1.0f);
}